// round 11
// baseline (speedup 1.0000x reference)
#include <cuda_runtime.h>
#include <cuda_bf16.h>
#include <math.h>
#include <stdint.h>

// ---------------------------------------------------------------------------
// Round 11: 16 warps + depth-2 gather pipeline with cp.async staging.
// In-flight gather data lives in SMEM (cp.async.ca 8B per corner,
// commit_group/wait_group<1> = depth-2), not registers -> 512 threads again.
// Enc plane is bf16 hi-only (ablation-proven safe); L0 uses 2-term MMA.
// ldmatrix B-frags, bf16x3 MMA for all other layers, register-fragment
// chaining, persistent grid.
// ---------------------------------------------------------------------------

#define LVLS 24
#define TSZ  (1u << 19)
#define P1   2654435761u
#define P2   805459861u

#define TILE_PTS  256
#define NTHREADS  512

#define CW   56                // enc plane stride (u16), conflict-free

#define WOFF_L0 0              // 64 x 56 (K=48)
#define WOFF_L1 3584           // 64 x 72
#define WOFF_L2 8192           // 64 x 72
#define WOFF_L3 12800          // 72 x 72 (N 65->72)
#define WOFF_R0 17984          // 64 x 88 (K=80, staged shifted by 1)
#define WOFF_R1 23616          // 64 x 72
#define WOFF_R2 28224          //  8 x 72 (N 3->8)

#define BOFF_L0 0
#define BOFF_L1 64
#define BOFF_L2 128
#define BOFF_L3 192
#define BOFF_R0 264
#define BOFF_R1 328
#define BOFF_R2 392

#define SO_WHI  0
#define SO_WLO  57600
#define SO_BIAS 115200
#define SO_CHI  116800                        // 256*56*2 = 28672 B (hi only)
#define SO_STG  145472                        // 16 warps * 2 slots * 2048 B
#define SMEM_BYTES (SO_STG + 16 * 2 * 2048)   // 211008

struct ResArr { float r[LVLS]; };
struct WPtrs  { const float* w[14]; };

typedef unsigned short u16;
typedef unsigned int   u32;

__device__ __forceinline__ float gelu_exact(float x) {
    return 0.5f * x * (1.0f + erff(x * 0.70710678118654752440f));
}
__device__ __forceinline__ float softplus_f(float x) {
    return fmaxf(x, 0.0f) + log1pf(expf(-fabsf(x)));
}
__device__ __forceinline__ float sigmoid_f(float x) {
    return 1.0f / (1.0f + expf(-x));
}

#define MMA_BF16(d, a0, a1, a2, a3, b0, b1)                                   \
    asm volatile(                                                             \
        "mma.sync.aligned.m16n8k16.row.col.f32.bf16.bf16.f32 "                \
        "{%0,%1,%2,%3}, {%4,%5,%6,%7}, {%8,%9}, {%0,%1,%2,%3};"               \
        : "+f"(d[0]), "+f"(d[1]), "+f"(d[2]), "+f"(d[3])                      \
        : "r"(a0), "r"(a1), "r"(a2), "r"(a3), "r"(b0), "r"(b1))

#define LDSM_X4(r0, r1, r2, r3, addr)                                         \
    asm volatile("ldmatrix.sync.aligned.m8n8.x4.shared.b16 {%0,%1,%2,%3}, [%4];" \
        : "=r"(r0), "=r"(r1), "=r"(r2), "=r"(r3) : "r"(addr))

#define LDSM_X2(r0, r1, addr)                                                 \
    asm volatile("ldmatrix.sync.aligned.m8n8.x2.shared.b16 {%0,%1}, [%2];"    \
        : "=r"(r0), "=r"(r1) : "r"(addr))

__device__ __forceinline__ void pack_split2(float v0, float v1,
                                            u32& h, u32& l) {
    u32 hh;
    asm("cvt.rn.bf16x2.f32 %0, %1, %2;" : "=r"(hh) : "f"(v1), "f"(v0));
    float f0 = __uint_as_float(hh << 16);
    float f1 = __uint_as_float(hh & 0xffff0000u);
    asm("cvt.rn.bf16x2.f32 %0, %1, %2;" : "=r"(l) : "f"(v1 - f1), "f"(v0 - f0));
    h = hh;
}

template<int KP>
__device__ __forceinline__ u32 lane_adj(int lane) {
    int row8  = lane & 7;
    int which = lane >> 3;
    int n_off = ((which & 2) << 2) + row8;
    int k_off = (which & 1) << 3;
    return (u32)((n_off * KP + k_off) * 2);
}

// generic 3-term layer (activation hi/lo in registers)
template<int K0, int K1, int NT, int KP, bool INIT>
__device__ __forceinline__ void run_layer_lds(const u32* __restrict__ ah,
                                              const u32* __restrict__ al,
                                              u32 shi, u32 slo,
                                              const float* __restrict__ bias,
                                              float (&acc)[NT][4], int qm)
{
    if (INIT) {
#pragma unroll
        for (int nt = 0; nt < NT; nt++) {
            float b0 = bias[nt * 8 + 2 * qm];
            float b1 = bias[nt * 8 + 2 * qm + 1];
            acc[nt][0] = b0; acc[nt][1] = b1;
            acc[nt][2] = b0; acc[nt][3] = b1;
        }
    }
#pragma unroll
    for (int kt = K0; kt < K1; kt++) {
#pragma unroll
        for (int p = 0; p < NT / 2; p++) {
            u32 off = (u32)((p * 16 * KP + kt * 16) * 2);
            u32 bh0, bh1, bh2, bh3, bl0, bl1, bl2, bl3;
            LDSM_X4(bh0, bh1, bh2, bh3, shi + off);
            LDSM_X4(bl0, bl1, bl2, bl3, slo + off);
            MMA_BF16(acc[2*p], ah[4*kt], ah[4*kt+1], ah[4*kt+2], ah[4*kt+3], bh0, bh1);
            MMA_BF16(acc[2*p], ah[4*kt], ah[4*kt+1], ah[4*kt+2], ah[4*kt+3], bl0, bl1);
            MMA_BF16(acc[2*p], al[4*kt], al[4*kt+1], al[4*kt+2], al[4*kt+3], bh0, bh1);
            MMA_BF16(acc[2*p+1], ah[4*kt], ah[4*kt+1], ah[4*kt+2], ah[4*kt+3], bh2, bh3);
            MMA_BF16(acc[2*p+1], ah[4*kt], ah[4*kt+1], ah[4*kt+2], ah[4*kt+3], bl2, bl3);
            MMA_BF16(acc[2*p+1], al[4*kt], al[4*kt+1], al[4*kt+2], al[4*kt+3], bh2, bh3);
        }
        if (NT & 1) {
            u32 off = (u32)(((NT - 1) * 8 * KP + kt * 16) * 2);
            u32 bh0, bh1, bl0, bl1;
            LDSM_X2(bh0, bh1, shi + off);
            LDSM_X2(bl0, bl1, slo + off);
            MMA_BF16(acc[NT-1], ah[4*kt], ah[4*kt+1], ah[4*kt+2], ah[4*kt+3], bh0, bh1);
            MMA_BF16(acc[NT-1], ah[4*kt], ah[4*kt+1], ah[4*kt+2], ah[4*kt+3], bl0, bl1);
            MMA_BF16(acc[NT-1], al[4*kt], al[4*kt+1], al[4*kt+2], al[4*kt+3], bh0, bh1);
        }
    }
}

// L0: A is bf16-only (enc), 2-term (Ahi*Bhi + Ahi*Blo)
template<int K0, int K1, int NT, int KP, bool INIT>
__device__ __forceinline__ void run_layer_l0(const u32* __restrict__ ah,
                                             u32 shi, u32 slo,
                                             const float* __restrict__ bias,
                                             float (&acc)[NT][4], int qm)
{
    if (INIT) {
#pragma unroll
        for (int nt = 0; nt < NT; nt++) {
            float b0 = bias[nt * 8 + 2 * qm];
            float b1 = bias[nt * 8 + 2 * qm + 1];
            acc[nt][0] = b0; acc[nt][1] = b1;
            acc[nt][2] = b0; acc[nt][3] = b1;
        }
    }
#pragma unroll
    for (int kt = K0; kt < K1; kt++) {
#pragma unroll
        for (int p = 0; p < NT / 2; p++) {
            u32 off = (u32)((p * 16 * KP + kt * 16) * 2);
            u32 bh0, bh1, bh2, bh3, bl0, bl1, bl2, bl3;
            LDSM_X4(bh0, bh1, bh2, bh3, shi + off);
            LDSM_X4(bl0, bl1, bl2, bl3, slo + off);
            MMA_BF16(acc[2*p], ah[4*kt], ah[4*kt+1], ah[4*kt+2], ah[4*kt+3], bh0, bh1);
            MMA_BF16(acc[2*p], ah[4*kt], ah[4*kt+1], ah[4*kt+2], ah[4*kt+3], bl0, bl1);
            MMA_BF16(acc[2*p+1], ah[4*kt], ah[4*kt+1], ah[4*kt+2], ah[4*kt+3], bh2, bh3);
            MMA_BF16(acc[2*p+1], ah[4*kt], ah[4*kt+1], ah[4*kt+2], ah[4*kt+3], bl2, bl3);
        }
    }
}

template<int KTN>
__device__ __forceinline__ void frags_gelu(const float (*acc)[4],
                                           u32* ah, u32* al)
{
#pragma unroll
    for (int kt = 0; kt < KTN; kt++) {
        pack_split2(gelu_exact(acc[2*kt][0]),   gelu_exact(acc[2*kt][1]),
                    ah[4*kt+0], al[4*kt+0]);
        pack_split2(gelu_exact(acc[2*kt][2]),   gelu_exact(acc[2*kt][3]),
                    ah[4*kt+1], al[4*kt+1]);
        pack_split2(gelu_exact(acc[2*kt+1][0]), gelu_exact(acc[2*kt+1][1]),
                    ah[4*kt+2], al[4*kt+2]);
        pack_split2(gelu_exact(acc[2*kt+1][2]), gelu_exact(acc[2*kt+1][3]),
                    ah[4*kt+3], al[4*kt+3]);
    }
}

// ---- cp.async gather: staging [warp][slot][corner][lane*8B] ----
__device__ __forceinline__ void gather_issue_cp(const float* __restrict__ table,
                                                float rl, float x0, float y0,
                                                float z0, int l, u32 stg_slot,
                                                float& wx, float& wy, float& wz)
{
    float posx = x0 * rl, posy = y0 * rl, posz = z0 * rl;
    float fx = floorf(posx), fy = floorf(posy), fz = floorf(posz);
    wx = posx - fx; wy = posy - fy; wz = posz - fz;
    unsigned ux = (unsigned)fx, uy = (unsigned)fy, uz = (unsigned)fz;
    unsigned hX[2] = {ux, ux + 1u};
    unsigned hY[2] = {uy * P1, (uy + 1u) * P1};
    unsigned hZ[2] = {uz * P2, (uz + 1u) * P2};
    const float2* tb = (const float2*)table + (size_t)l * TSZ;
#pragma unroll
    for (int c = 0; c < 8; c++) {
        int bx = (c >> 2) & 1, by = (c >> 1) & 1, bz = c & 1;
        unsigned idx = (hX[bx] ^ hY[by] ^ hZ[bz]) & (TSZ - 1u);
        asm volatile("cp.async.ca.shared.global [%0], [%1], 8;"
            :: "r"(stg_slot + c * 256), "l"(tb + idx));
    }
    asm volatile("cp.async.commit_group;" ::: "memory");
}

template<int WG>
__device__ __forceinline__ void gather_consume_cp(u16* __restrict__ chi,
                                                  int row, int l, u32 stg_slot,
                                                  float wx, float wy, float wz)
{
    asm volatile("cp.async.wait_group %0;" :: "n"(WG) : "memory");
    float wX[2] = {1.0f - wx, wx};
    float wY[2] = {1.0f - wy, wy};
    float wZ[2] = {1.0f - wz, wz};
    float a0 = 0.0f, a1 = 0.0f;
#pragma unroll
    for (int c = 0; c < 8; c++) {
        float fx, fy;
        asm volatile("ld.shared.v2.f32 {%0,%1}, [%2];"
            : "=f"(fx), "=f"(fy) : "r"(stg_slot + c * 256));
        int bx = (c >> 2) & 1, by = (c >> 1) & 1, bz = c & 1;
        float wt = wX[bx] * wY[by] * wZ[bz];
        a0 = fmaf(fx, wt, a0);
        a1 = fmaf(fy, wt, a1);
    }
    u32 h;
    asm("cvt.rn.bf16x2.f32 %0, %1, %2;" : "=r"(h) : "f"(a1), "f"(a0));
    *(u32*)(chi + row * CW + 2 * l) = h;
}

// ---- staging ----
__device__ void stage_w(const float* __restrict__ g, u16* hi, u16* lo,
                        int realK, int realN, int K, int NPAD, int KP, int tid)
{
    for (int idx = tid; idx < NPAD * K; idx += NTHREADS) {
        int nn = idx / K, kk = idx % K;
        float v = (kk < realK && nn < realN) ? g[kk * realN + nn] : 0.0f;
        u32 h, l;
        pack_split2(v, 0.0f, h, l);
        hi[nn * KP + kk] = (u16)(h & 0xffff);
        lo[nn * KP + kk] = (u16)(l & 0xffff);
    }
}
__device__ void stage_w_shift(const float* __restrict__ g, u16* hi, u16* lo,
                              int tid)
{
    const int K = 80, KP = 88;
    for (int idx = tid; idx < 64 * K; idx += NTHREADS) {
        int nn = idx / K, kk = idx % K;
        float v = (kk >= 1 && kk <= 73) ? g[(kk - 1) * 64 + nn] : 0.0f;
        u32 h, l;
        pack_split2(v, 0.0f, h, l);
        hi[nn * KP + kk] = (u16)(h & 0xffff);
        lo[nn * KP + kk] = (u16)(l & 0xffff);
    }
}
__device__ void stage_b(const float* __restrict__ g, float* dst,
                        int realN, int NPAD, int tid)
{
    for (int i = tid; i < NPAD; i += NTHREADS)
        dst[i] = (i < realN) ? g[i] : 0.0f;
}

__global__ void __launch_bounds__(NTHREADS, 1)
nerf_tc_kernel(const float* __restrict__ pts,
               const float* __restrict__ dirs,
               const float* __restrict__ table,
               WPtrs prm, ResArr res,
               float* __restrict__ out, int n)
{
    extern __shared__ char smem[];
    u16*   whi  = (u16*)(smem + SO_WHI);
    u16*   wlo  = (u16*)(smem + SO_WLO);
    float* bias = (float*)(smem + SO_BIAS);
    u16*   chi  = (u16*)(smem + SO_CHI);

    const int tid  = threadIdx.x;
    const int warp = tid >> 5;
    const int lane = tid & 31;
    const int qr = lane >> 2, qm = lane & 3;
    const int rg = warp;

    stage_w(prm.w[0],  whi + WOFF_L0, wlo + WOFF_L0, 48, 64, 48, 64, 56, tid);
    stage_w(prm.w[2],  whi + WOFF_L1, wlo + WOFF_L1, 64, 64, 64, 64, 72, tid);
    stage_w(prm.w[4],  whi + WOFF_L2, wlo + WOFF_L2, 64, 64, 64, 64, 72, tid);
    stage_w(prm.w[6],  whi + WOFF_L3, wlo + WOFF_L3, 64, 65, 64, 72, 72, tid);
    stage_w_shift(prm.w[8], whi + WOFF_R0, wlo + WOFF_R0, tid);
    stage_w(prm.w[10], whi + WOFF_R1, wlo + WOFF_R1, 64, 64, 64, 64, 72, tid);
    stage_w(prm.w[12], whi + WOFF_R2, wlo + WOFF_R2, 64,  3, 64,  8, 72, tid);
    stage_b(prm.w[1],  bias + BOFF_L0, 64, 64, tid);
    stage_b(prm.w[3],  bias + BOFF_L1, 64, 64, tid);
    stage_b(prm.w[5],  bias + BOFF_L2, 64, 64, tid);
    stage_b(prm.w[7],  bias + BOFF_L3, 65, 72, tid);
    stage_b(prm.w[9],  bias + BOFF_R0, 64, 64, tid);
    stage_b(prm.w[11], bias + BOFF_R1, 64, 64, tid);
    stage_b(prm.w[13], bias + BOFF_R2,  3,  8, tid);
    __syncthreads();

    u16* Chi = chi + rg * 16 * CW;

    const u32 whi_s = (u32)__cvta_generic_to_shared(whi);
    const u32 wlo_s = (u32)__cvta_generic_to_shared(wlo);
    const u32 adj56 = lane_adj<56>(lane);
    const u32 adj72 = lane_adj<72>(lane);
    const u32 adj88 = lane_adj<88>(lane);
    const u32 sL0h = whi_s + WOFF_L0*2 + adj56, sL0l = wlo_s + WOFF_L0*2 + adj56;
    const u32 sL1h = whi_s + WOFF_L1*2 + adj72, sL1l = wlo_s + WOFF_L1*2 + adj72;
    const u32 sL2h = whi_s + WOFF_L2*2 + adj72, sL2l = wlo_s + WOFF_L2*2 + adj72;
    const u32 sL3h = whi_s + WOFF_L3*2 + adj72, sL3l = wlo_s + WOFF_L3*2 + adj72;
    const u32 sR0h = whi_s + WOFF_R0*2 + adj88, sR0l = wlo_s + WOFF_R0*2 + adj88;
    const u32 sR1h = whi_s + WOFF_R1*2 + adj72, sR1l = wlo_s + WOFF_R1*2 + adj72;
    const u32 sR2h = whi_s + WOFF_R2*2 + adj72, sR2l = wlo_s + WOFF_R2*2 + adj72;

    // staging base for this lane: [warp][slot][corner][lane]
    const u32 stg0 = (u32)__cvta_generic_to_shared(smem + SO_STG)
                     + warp * 4096 + lane * 8;
    const u32 stg1 = stg0 + 2048;

    const int ntiles = n / TILE_PTS;
    const int grow = lane >> 1;               // 2 lanes per point
    const int gpar = lane & 1;                // level parity
    float w0x, w0y, w0z, w1x, w1y, w1z;
    float gx0, gy0, gz0;

    int tile = blockIdx.x;
    if (tile >= ntiles) return;

    // ---- prologue: full 24-level gather of first tile (depth-2 cp.async) ----
    {
        int gpt = tile * TILE_PTS + rg * 16 + grow;
        gx0 = (pts[gpt * 3 + 0] + 1.0f) * 0.5f;
        gy0 = (pts[gpt * 3 + 1] + 1.0f) * 0.5f;
        gz0 = (pts[gpt * 3 + 2] + 1.0f) * 0.5f;
        gather_issue_cp(table, res.r[gpar],     gx0, gy0, gz0, gpar,     stg0,
                        w0x, w0y, w0z);
        gather_issue_cp(table, res.r[2 + gpar], gx0, gy0, gz0, 2 + gpar, stg1,
                        w1x, w1y, w1z);
#pragma unroll 1
        for (int c = 0; c < 10; c++) {
            int gl = 2 * c + gpar;
            if (c & 1) {
                gather_consume_cp<1>(Chi, grow, gl, stg1, w1x, w1y, w1z);
                gather_issue_cp(table, res.r[gl + 4], gx0, gy0, gz0, gl + 4,
                                stg1, w1x, w1y, w1z);
            } else {
                gather_consume_cp<1>(Chi, grow, gl, stg0, w0x, w0y, w0z);
                gather_issue_cp(table, res.r[gl + 4], gx0, gy0, gz0, gl + 4,
                                stg0, w0x, w0y, w0z);
            }
        }
        gather_consume_cp<1>(Chi, grow, 20 + gpar, stg0, w0x, w0y, w0z);
        gather_consume_cp<0>(Chi, grow, 22 + gpar, stg1, w1x, w1y, w1z);
    }
    __syncwarp();

    while (true) {
        const int base = tile * TILE_PTS;
        const int next = tile + gridDim.x;
        const bool g = (next < ntiles);

        u32 ah[20], al[20];

        // L0 A-frags from enc plane (hi only)
        {
            const u16* pc = Chi + qr * CW + 2 * qm;
#pragma unroll
            for (int kt = 0; kt < 3; kt++) {
                ah[4*kt+0] = *(const u32*)(pc + kt * 16);
                ah[4*kt+1] = *(const u32*)(pc + kt * 16 + 8 * CW);
                ah[4*kt+2] = *(const u32*)(pc + kt * 16 + 8);
                ah[4*kt+3] = *(const u32*)(pc + kt * 16 + 8 * CW + 8);
            }
        }

        float acc[8][4];
        // L0a
        run_layer_l0<0, 2, 8, 56, true>(ah, sL0h, sL0l, bias + BOFF_L0,
                                        acc, qm);
        if (g) {   // slot0: next-tile coords + issue(0)
            int gpt = next * TILE_PTS + rg * 16 + grow;
            gx0 = (pts[gpt * 3 + 0] + 1.0f) * 0.5f;
            gy0 = (pts[gpt * 3 + 1] + 1.0f) * 0.5f;
            gz0 = (pts[gpt * 3 + 2] + 1.0f) * 0.5f;
            gather_issue_cp(table, res.r[gpar], gx0, gy0, gz0, gpar, stg0,
                            w0x, w0y, w0z);
        }
        // L0b
        run_layer_l0<2, 3, 8, 56, false>(ah, sL0h, sL0l, bias + BOFF_L0,
                                         acc, qm);
        __syncwarp();   // all lanes done reading C plane
        if (g)          // slot1: issue(1)
            gather_issue_cp(table, res.r[2 + gpar], gx0, gy0, gz0, 2 + gpar,
                            stg1, w1x, w1y, w1z);

        // L1
        frags_gelu<4>(acc, ah, al);
        run_layer_lds<0, 2, 8, 72, true>(ah, al, sL1h, sL1l,
                                         bias + BOFF_L1, acc, qm);
        if (g) {        // slot2: consume(0), issue(2)
            gather_consume_cp<1>(Chi, grow, gpar, stg0, w0x, w0y, w0z);
            gather_issue_cp(table, res.r[4 + gpar], gx0, gy0, gz0, 4 + gpar,
                            stg0, w0x, w0y, w0z);
        }
        run_layer_lds<2, 4, 8, 72, false>(ah, al, sL1h, sL1l,
                                          bias + BOFF_L1, acc, qm);
        if (g) {        // slot3: consume(1), issue(3)
            gather_consume_cp<1>(Chi, grow, 2 + gpar, stg1, w1x, w1y, w1z);
            gather_issue_cp(table, res.r[6 + gpar], gx0, gy0, gz0, 6 + gpar,
                            stg1, w1x, w1y, w1z);
        }

        // L2
        frags_gelu<4>(acc, ah, al);
        run_layer_lds<0, 2, 8, 72, true>(ah, al, sL2h, sL2l,
                                         bias + BOFF_L2, acc, qm);
        if (g) {        // slot4: consume(2), issue(4)
            gather_consume_cp<1>(Chi, grow, 4 + gpar, stg0, w0x, w0y, w0z);
            gather_issue_cp(table, res.r[8 + gpar], gx0, gy0, gz0, 8 + gpar,
                            stg0, w0x, w0y, w0z);
        }
        run_layer_lds<2, 4, 8, 72, false>(ah, al, sL2h, sL2l,
                                          bias + BOFF_L2, acc, qm);
        if (g) {        // slot5: consume(3), issue(5)
            gather_consume_cp<1>(Chi, grow, 6 + gpar, stg1, w1x, w1y, w1z);
            gather_issue_cp(table, res.r[10 + gpar], gx0, gy0, gz0, 10 + gpar,
                            stg1, w1x, w1y, w1z);
        }

        // L3 (NT=9)
        frags_gelu<4>(acc, ah, al);
        float acc9[9][4];
        run_layer_lds<0, 2, 9, 72, true>(ah, al, sL3h, sL3l,
                                         bias + BOFF_L3, acc9, qm);
        if (g) {        // slot6: consume(4), issue(6)
            gather_consume_cp<1>(Chi, grow, 8 + gpar, stg0, w0x, w0y, w0z);
            gather_issue_cp(table, res.r[12 + gpar], gx0, gy0, gz0, 12 + gpar,
                            stg0, w0x, w0y, w0z);
        }
        run_layer_lds<2, 4, 9, 72, false>(ah, al, sL3h, sL3l,
                                          bias + BOFF_L3, acc9, qm);
        if (g) {        // slot7: consume(5), issue(7)
            gather_consume_cp<1>(Chi, grow, 10 + gpar, stg1, w1x, w1y, w1z);
            gather_issue_cp(table, res.r[14 + gpar], gx0, gy0, gz0, 14 + gpar,
                            stg1, w1x, w1y, w1z);
        }

        // density out
        if (qm == 0) {
            int pA = base + rg * 16 + qr;
            out[(size_t)3 * n + pA]     = softplus_f(acc9[0][0]);
            out[(size_t)3 * n + pA + 8] = softplus_f(acc9[0][2]);
        }
        // SH for rows qr and qr+8
        float shA[9], shB[9];
        {
            int gA = base + rg * 16 + qr;
            int gB = gA + 8;
            float dxA = dirs[gA * 3 + 0], dyA = dirs[gA * 3 + 1],
                  dzA = dirs[gA * 3 + 2];
            float dxB = dirs[gB * 3 + 0], dyB = dirs[gB * 3 + 1],
                  dzB = dirs[gB * 3 + 2];
            shA[0] = 0.28209479177387814f;
            shA[1] = -0.48860251190291987f * dyA;
            shA[2] =  0.48860251190291987f * dzA;
            shA[3] = -0.48860251190291987f * dxA;
            shA[4] =  1.0925484305920792f  * dxA * dyA;
            shA[5] = -1.0925484305920792f  * dyA * dzA;
            shA[6] =  0.31539156525252005f * (3.0f * dzA * dzA - 1.0f);
            shA[7] = -1.0925484305920792f  * dxA * dzA;
            shA[8] =  0.5462742152960396f  * (dxA * dxA - dyA * dyA);
            shB[0] = 0.28209479177387814f;
            shB[1] = -0.48860251190291987f * dyB;
            shB[2] =  0.48860251190291987f * dzB;
            shB[3] = -0.48860251190291987f * dxB;
            shB[4] =  1.0925484305920792f  * dxB * dyB;
            shB[5] = -1.0925484305920792f  * dyB * dzB;
            shB[6] =  0.31539156525252005f * (3.0f * dzB * dzB - 1.0f);
            shB[7] = -1.0925484305920792f  * dxB * dzB;
            shB[8] =  0.5462742152960396f  * (dxB * dxB - dyB * dyB);
        }
        // R0 A-frags: cols 0..63 gelu(fad), k-tile 4 = col64 + SH
        frags_gelu<4>(acc9, ah, al);
        {
            float e64A = gelu_exact(acc9[8][0]);
            float e64B = gelu_exact(acc9[8][2]);
            float v0A, v1A, v2A, v3A, v0B, v1B, v2B, v3B;
            if (qm == 0) {
                v0A = e64A;   v1A = shA[0]; v2A = shA[7]; v3A = shA[8];
                v0B = e64B;   v1B = shB[0]; v2B = shB[7]; v3B = shB[8];
            } else if (qm == 1) {
                v0A = shA[1]; v1A = shA[2]; v2A = 0.0f;   v3A = 0.0f;
                v0B = shB[1]; v1B = shB[2]; v2B = 0.0f;   v3B = 0.0f;
            } else if (qm == 2) {
                v0A = shA[3]; v1A = shA[4]; v2A = 0.0f;   v3A = 0.0f;
                v0B = shB[3]; v1B = shB[4]; v2B = 0.0f;   v3B = 0.0f;
            } else {
                v0A = shA[5]; v1A = shA[6]; v2A = 0.0f;   v3A = 0.0f;
                v0B = shB[5]; v1B = shB[6]; v2B = 0.0f;   v3B = 0.0f;
            }
            pack_split2(v0A, v1A, ah[16], al[16]);
            pack_split2(v0B, v1B, ah[17], al[17]);
            pack_split2(v2A, v3A, ah[18], al[18]);
            pack_split2(v2B, v3B, ah[19], al[19]);
        }
        if (g) {        // slot8: consume(6), issue(8)
            gather_consume_cp<1>(Chi, grow, 12 + gpar, stg0, w0x, w0y, w0z);
            gather_issue_cp(table, res.r[16 + gpar], gx0, gy0, gz0, 16 + gpar,
                            stg0, w0x, w0y, w0z);
        }

        // R0 (K=80)
        run_layer_lds<0, 3, 8, 88, true>(ah, al, sR0h, sR0l,
                                         bias + BOFF_R0, acc, qm);
        if (g) {        // slot9: consume(7), issue(9)
            gather_consume_cp<1>(Chi, grow, 14 + gpar, stg1, w1x, w1y, w1z);
            gather_issue_cp(table, res.r[18 + gpar], gx0, gy0, gz0, 18 + gpar,
                            stg1, w1x, w1y, w1z);
        }
        run_layer_lds<3, 5, 8, 88, false>(ah, al, sR0h, sR0l,
                                          bias + BOFF_R0, acc, qm);
        if (g) {        // slot10: consume(8), issue(10)
            gather_consume_cp<1>(Chi, grow, 16 + gpar, stg0, w0x, w0y, w0z);
            gather_issue_cp(table, res.r[20 + gpar], gx0, gy0, gz0, 20 + gpar,
                            stg0, w0x, w0y, w0z);
        }

        // R1
        frags_gelu<4>(acc, ah, al);
        run_layer_lds<0, 2, 8, 72, true>(ah, al, sR1h, sR1l,
                                         bias + BOFF_R1, acc, qm);
        if (g) {        // slot11: consume(9), issue(11)
            gather_consume_cp<1>(Chi, grow, 18 + gpar, stg1, w1x, w1y, w1z);
            gather_issue_cp(table, res.r[22 + gpar], gx0, gy0, gz0, 22 + gpar,
                            stg1, w1x, w1y, w1z);
        }
        run_layer_lds<2, 4, 8, 72, false>(ah, al, sR1h, sR1l,
                                          bias + BOFF_R1, acc, qm);
        if (g)          // slot12: consume(10)
            gather_consume_cp<1>(Chi, grow, 20 + gpar, stg0, w0x, w0y, w0z);

        // R2
        frags_gelu<4>(acc, ah, al);
        {
            float acc1[1][4];
            run_layer_lds<0, 4, 1, 72, true>(ah, al, sR2h, sR2l,
                                             bias + BOFF_R2, acc1, qm);
            int pt0 = base + rg * 16 + qr;
            int pt1 = pt0 + 8;
            if (qm == 0) {
                out[pt0 * 3 + 0] = sigmoid_f(acc1[0][0]);
                out[pt0 * 3 + 1] = sigmoid_f(acc1[0][1]);
                out[pt1 * 3 + 0] = sigmoid_f(acc1[0][2]);
                out[pt1 * 3 + 1] = sigmoid_f(acc1[0][3]);
            } else if (qm == 1) {
                out[pt0 * 3 + 2] = sigmoid_f(acc1[0][0]);
                out[pt1 * 3 + 2] = sigmoid_f(acc1[0][2]);
            }
        }
        if (g)          // slot13: consume(11), drain
            gather_consume_cp<0>(Chi, grow, 22 + gpar, stg1, w1x, w1y, w1z);
        __syncwarp();

        if (!g) break;
        tile = next;
    }
}

extern "C" void kernel_launch(void* const* d_in, const int* in_sizes, int n_in,
                              void* d_out, int out_size)
{
    const float* pts   = (const float*)d_in[0];
    const float* dirs  = (const float*)d_in[1];
    const float* table = (const float*)d_in[2];

    WPtrs prm;
    for (int a = 0; a < 14; a++) prm.w[a] = (const float*)d_in[3 + a];

    int n = in_sizes[0] / 3;

    ResArr res;
    double b = exp((log(2048.0) - log(16.0)) / 23.0);
    for (int l = 0; l < LVLS; l++)
        res.r[l] = (float)floor(16.0 * pow(b, (double)l));

    cudaFuncSetAttribute(nerf_tc_kernel,
                         cudaFuncAttributeMaxDynamicSharedMemorySize, SMEM_BYTES);

    int dev = 0, sms = 148;
    cudaGetDevice(&dev);
    cudaDeviceGetAttribute(&sms, cudaDevAttrMultiProcessorCount, dev);
    int ntiles = n / TILE_PTS;
    int blocks = (sms < ntiles) ? sms : ntiles;

    nerf_tc_kernel<<<blocks, NTHREADS, SMEM_BYTES>>>(
        pts, dirs, table, prm, res, (float*)d_out, n);
}

// round 12
// speedup vs baseline: 2.1596x; 2.1596x over previous
#include <cuda_runtime.h>
#include <cuda_bf16.h>
#include <math.h>
#include <stdint.h>

// ---------------------------------------------------------------------------
// Round 12: TWO-KERNEL SPLIT.
// K1 gather: 1 thread per (point,level), 8 independent LDGs, full occupancy,
//            LTS-bound; writes enc as packed bf16x2 to __device__ scratch.
// K2 MLP:    R8 register-chained bf16x3 tensor pipeline, gather-free; L0
//            A-frags prefetched from scratch one tile ahead. 512 thr, 16
//            independent warps, no per-tile syncs.
// ---------------------------------------------------------------------------

#define LVLS 24
#define TSZ  (1u << 19)
#define P1   2654435761u
#define P2   805459861u

#define NPTS      524288
#define TILE_PTS  256
#define NTHREADS  512

#define WOFF_L0 0              // 64 x 56 (K=48)
#define WOFF_L1 3584           // 64 x 72
#define WOFF_L2 8192           // 64 x 72
#define WOFF_L3 12800          // 72 x 72 (N 65->72)
#define WOFF_R0 17984          // 64 x 88 (K=80, staged shifted by 1)
#define WOFF_R1 23616          // 64 x 72
#define WOFF_R2 28224          //  8 x 72 (N 3->8)

#define BOFF_L0 0
#define BOFF_L1 64
#define BOFF_L2 128
#define BOFF_L3 192
#define BOFF_R0 264
#define BOFF_R1 328
#define BOFF_R2 392

#define SO_WHI  0
#define SO_WLO  57600
#define SO_BIAS 115200
#define SMEM_BYTES (SO_BIAS + 400 * 4)        // 116800

struct ResArr { float r[LVLS]; };
struct WPtrs  { const float* w[14]; };

typedef unsigned short u16;
typedef unsigned int   u32;

// enc scratch: [point][level] packed bf16x2 (feat0, feat1) = 50 MB
__device__ u32 g_enc[(size_t)NPTS * LVLS];

__device__ __forceinline__ float gelu_exact(float x) {
    return 0.5f * x * (1.0f + erff(x * 0.70710678118654752440f));
}
__device__ __forceinline__ float softplus_f(float x) {
    return fmaxf(x, 0.0f) + log1pf(expf(-fabsf(x)));
}
__device__ __forceinline__ float sigmoid_f(float x) {
    return 1.0f / (1.0f + expf(-x));
}

#define MMA_BF16(d, a0, a1, a2, a3, b0, b1)                                   \
    asm volatile(                                                             \
        "mma.sync.aligned.m16n8k16.row.col.f32.bf16.bf16.f32 "                \
        "{%0,%1,%2,%3}, {%4,%5,%6,%7}, {%8,%9}, {%0,%1,%2,%3};"               \
        : "+f"(d[0]), "+f"(d[1]), "+f"(d[2]), "+f"(d[3])                      \
        : "r"(a0), "r"(a1), "r"(a2), "r"(a3), "r"(b0), "r"(b1))

#define LDSM_X4(r0, r1, r2, r3, addr)                                         \
    asm volatile("ldmatrix.sync.aligned.m8n8.x4.shared.b16 {%0,%1,%2,%3}, [%4];" \
        : "=r"(r0), "=r"(r1), "=r"(r2), "=r"(r3) : "r"(addr))

#define LDSM_X2(r0, r1, addr)                                                 \
    asm volatile("ldmatrix.sync.aligned.m8n8.x2.shared.b16 {%0,%1}, [%2];"    \
        : "=r"(r0), "=r"(r1) : "r"(addr))

__device__ __forceinline__ void pack_split2(float v0, float v1,
                                            u32& h, u32& l) {
    u32 hh;
    asm("cvt.rn.bf16x2.f32 %0, %1, %2;" : "=r"(hh) : "f"(v1), "f"(v0));
    float f0 = __uint_as_float(hh << 16);
    float f1 = __uint_as_float(hh & 0xffff0000u);
    asm("cvt.rn.bf16x2.f32 %0, %1, %2;" : "=r"(l) : "f"(v1 - f1), "f"(v0 - f0));
    h = hh;
}

template<int KP>
__device__ __forceinline__ u32 lane_adj(int lane) {
    int row8  = lane & 7;
    int which = lane >> 3;
    int n_off = ((which & 2) << 2) + row8;
    int k_off = (which & 1) << 3;
    return (u32)((n_off * KP + k_off) * 2);
}

// 3-term layer (activation hi/lo in registers)
template<int K0, int K1, int NT, int KP, bool INIT>
__device__ __forceinline__ void run_layer_lds(const u32* __restrict__ ah,
                                              const u32* __restrict__ al,
                                              u32 shi, u32 slo,
                                              const float* __restrict__ bias,
                                              float (&acc)[NT][4], int qm)
{
    if (INIT) {
#pragma unroll
        for (int nt = 0; nt < NT; nt++) {
            float b0 = bias[nt * 8 + 2 * qm];
            float b1 = bias[nt * 8 + 2 * qm + 1];
            acc[nt][0] = b0; acc[nt][1] = b1;
            acc[nt][2] = b0; acc[nt][3] = b1;
        }
    }
#pragma unroll
    for (int kt = K0; kt < K1; kt++) {
#pragma unroll
        for (int p = 0; p < NT / 2; p++) {
            u32 off = (u32)((p * 16 * KP + kt * 16) * 2);
            u32 bh0, bh1, bh2, bh3, bl0, bl1, bl2, bl3;
            LDSM_X4(bh0, bh1, bh2, bh3, shi + off);
            LDSM_X4(bl0, bl1, bl2, bl3, slo + off);
            MMA_BF16(acc[2*p], ah[4*kt], ah[4*kt+1], ah[4*kt+2], ah[4*kt+3], bh0, bh1);
            MMA_BF16(acc[2*p], ah[4*kt], ah[4*kt+1], ah[4*kt+2], ah[4*kt+3], bl0, bl1);
            MMA_BF16(acc[2*p], al[4*kt], al[4*kt+1], al[4*kt+2], al[4*kt+3], bh0, bh1);
            MMA_BF16(acc[2*p+1], ah[4*kt], ah[4*kt+1], ah[4*kt+2], ah[4*kt+3], bh2, bh3);
            MMA_BF16(acc[2*p+1], ah[4*kt], ah[4*kt+1], ah[4*kt+2], ah[4*kt+3], bl2, bl3);
            MMA_BF16(acc[2*p+1], al[4*kt], al[4*kt+1], al[4*kt+2], al[4*kt+3], bh2, bh3);
        }
        if (NT & 1) {
            u32 off = (u32)(((NT - 1) * 8 * KP + kt * 16) * 2);
            u32 bh0, bh1, bl0, bl1;
            LDSM_X2(bh0, bh1, shi + off);
            LDSM_X2(bl0, bl1, slo + off);
            MMA_BF16(acc[NT-1], ah[4*kt], ah[4*kt+1], ah[4*kt+2], ah[4*kt+3], bh0, bh1);
            MMA_BF16(acc[NT-1], ah[4*kt], ah[4*kt+1], ah[4*kt+2], ah[4*kt+3], bl0, bl1);
            MMA_BF16(acc[NT-1], al[4*kt], al[4*kt+1], al[4*kt+2], al[4*kt+3], bh0, bh1);
        }
    }
}

// L0: A is bf16-only (enc), 2-term
template<int NT, int KP>
__device__ __forceinline__ void run_layer_l0(const u32* __restrict__ ah,
                                             u32 shi, u32 slo,
                                             const float* __restrict__ bias,
                                             float (&acc)[NT][4], int qm)
{
#pragma unroll
    for (int nt = 0; nt < NT; nt++) {
        float b0 = bias[nt * 8 + 2 * qm];
        float b1 = bias[nt * 8 + 2 * qm + 1];
        acc[nt][0] = b0; acc[nt][1] = b1;
        acc[nt][2] = b0; acc[nt][3] = b1;
    }
#pragma unroll
    for (int kt = 0; kt < 3; kt++) {
#pragma unroll
        for (int p = 0; p < NT / 2; p++) {
            u32 off = (u32)((p * 16 * KP + kt * 16) * 2);
            u32 bh0, bh1, bh2, bh3, bl0, bl1, bl2, bl3;
            LDSM_X4(bh0, bh1, bh2, bh3, shi + off);
            LDSM_X4(bl0, bl1, bl2, bl3, slo + off);
            MMA_BF16(acc[2*p], ah[4*kt], ah[4*kt+1], ah[4*kt+2], ah[4*kt+3], bh0, bh1);
            MMA_BF16(acc[2*p], ah[4*kt], ah[4*kt+1], ah[4*kt+2], ah[4*kt+3], bl0, bl1);
            MMA_BF16(acc[2*p+1], ah[4*kt], ah[4*kt+1], ah[4*kt+2], ah[4*kt+3], bh2, bh3);
            MMA_BF16(acc[2*p+1], ah[4*kt], ah[4*kt+1], ah[4*kt+2], ah[4*kt+3], bl2, bl3);
        }
    }
}

template<int KTN>
__device__ __forceinline__ void frags_gelu(const float (*acc)[4],
                                           u32* ah, u32* al)
{
#pragma unroll
    for (int kt = 0; kt < KTN; kt++) {
        pack_split2(gelu_exact(acc[2*kt][0]),   gelu_exact(acc[2*kt][1]),
                    ah[4*kt+0], al[4*kt+0]);
        pack_split2(gelu_exact(acc[2*kt][2]),   gelu_exact(acc[2*kt][3]),
                    ah[4*kt+1], al[4*kt+1]);
        pack_split2(gelu_exact(acc[2*kt+1][0]), gelu_exact(acc[2*kt+1][1]),
                    ah[4*kt+2], al[4*kt+2]);
        pack_split2(gelu_exact(acc[2*kt+1][2]), gelu_exact(acc[2*kt+1][3]),
                    ah[4*kt+3], al[4*kt+3]);
    }
}

// ============================ KERNEL 1: gather ============================
// blockDim = 192 (8 points x 24 levels). One thread per (point, level).
__global__ void __launch_bounds__(192, 8)
gather_kernel(const float* __restrict__ pts,
              const float* __restrict__ table,
              ResArr res, int n)
{
    int t = blockIdx.x * 192 + threadIdx.x;
    int p = t / LVLS;
    int l = t - p * LVLS;
    if (p >= n) return;

    float x0 = (pts[p * 3 + 0] + 1.0f) * 0.5f;
    float y0 = (pts[p * 3 + 1] + 1.0f) * 0.5f;
    float z0 = (pts[p * 3 + 2] + 1.0f) * 0.5f;

    float rl = res.r[l];
    float posx = x0 * rl, posy = y0 * rl, posz = z0 * rl;
    float fx = floorf(posx), fy = floorf(posy), fz = floorf(posz);
    float wx = posx - fx, wy = posy - fy, wz = posz - fz;
    unsigned ux = (unsigned)fx, uy = (unsigned)fy, uz = (unsigned)fz;
    unsigned hX[2] = {ux, ux + 1u};
    unsigned hY[2] = {uy * P1, (uy + 1u) * P1};
    unsigned hZ[2] = {uz * P2, (uz + 1u) * P2};
    float wX[2] = {1.0f - wx, wx};
    float wY[2] = {1.0f - wy, wy};
    float wZ[2] = {1.0f - wz, wz};
    const float2* tb = (const float2*)table + (size_t)l * TSZ;

    float2 f[8]; float wt[8];
#pragma unroll
    for (int c = 0; c < 8; c++) {
        int bx = (c >> 2) & 1, by = (c >> 1) & 1, bz = c & 1;
        unsigned idx = (hX[bx] ^ hY[by] ^ hZ[bz]) & (TSZ - 1u);
        f[c]  = __ldg(tb + idx);
        wt[c] = wX[bx] * wY[by] * wZ[bz];
    }
    float a0 = 0.0f, a1 = 0.0f;
#pragma unroll
    for (int c = 0; c < 8; c++) {
        a0 = fmaf(f[c].x, wt[c], a0);
        a1 = fmaf(f[c].y, wt[c], a1);
    }
    u32 h;
    asm("cvt.rn.bf16x2.f32 %0, %1, %2;" : "=r"(h) : "f"(a1), "f"(a0));
    g_enc[(size_t)p * LVLS + l] = h;
}

// ============================ KERNEL 2: MLP ===============================
// staging helpers
__device__ void stage_w(const float* __restrict__ g, u16* hi, u16* lo,
                        int realK, int realN, int K, int NPAD, int KP, int tid)
{
    for (int idx = tid; idx < NPAD * K; idx += NTHREADS) {
        int nn = idx / K, kk = idx % K;
        float v = (kk < realK && nn < realN) ? g[kk * realN + nn] : 0.0f;
        u32 h, l;
        pack_split2(v, 0.0f, h, l);
        hi[nn * KP + kk] = (u16)(h & 0xffff);
        lo[nn * KP + kk] = (u16)(l & 0xffff);
    }
}
__device__ void stage_w_shift(const float* __restrict__ g, u16* hi, u16* lo,
                              int tid)
{
    const int K = 80, KP = 88;
    for (int idx = tid; idx < 64 * K; idx += NTHREADS) {
        int nn = idx / K, kk = idx % K;
        float v = (kk >= 1 && kk <= 73) ? g[(kk - 1) * 64 + nn] : 0.0f;
        u32 h, l;
        pack_split2(v, 0.0f, h, l);
        hi[nn * KP + kk] = (u16)(h & 0xffff);
        lo[nn * KP + kk] = (u16)(l & 0xffff);
    }
}
__device__ void stage_b(const float* __restrict__ g, float* dst,
                        int realN, int NPAD, int tid)
{
    for (int i = tid; i < NPAD; i += NTHREADS)
        dst[i] = (i < realN) ? g[i] : 0.0f;
}

__global__ void __launch_bounds__(NTHREADS, 1)
mlp_kernel(const float* __restrict__ dirs,
           WPtrs prm,
           float* __restrict__ out, int n)
{
    extern __shared__ char smem[];
    u16*   whi  = (u16*)(smem + SO_WHI);
    u16*   wlo  = (u16*)(smem + SO_WLO);
    float* bias = (float*)(smem + SO_BIAS);

    const int tid  = threadIdx.x;
    const int warp = tid >> 5;
    const int lane = tid & 31;
    const int qr = lane >> 2, qm = lane & 3;
    const int rg = warp;

    stage_w(prm.w[0],  whi + WOFF_L0, wlo + WOFF_L0, 48, 64, 48, 64, 56, tid);
    stage_w(prm.w[2],  whi + WOFF_L1, wlo + WOFF_L1, 64, 64, 64, 64, 72, tid);
    stage_w(prm.w[4],  whi + WOFF_L2, wlo + WOFF_L2, 64, 64, 64, 64, 72, tid);
    stage_w(prm.w[6],  whi + WOFF_L3, wlo + WOFF_L3, 64, 65, 64, 72, 72, tid);
    stage_w_shift(prm.w[8], whi + WOFF_R0, wlo + WOFF_R0, tid);
    stage_w(prm.w[10], whi + WOFF_R1, wlo + WOFF_R1, 64, 64, 64, 64, 72, tid);
    stage_w(prm.w[12], whi + WOFF_R2, wlo + WOFF_R2, 64,  3, 64,  8, 72, tid);
    stage_b(prm.w[1],  bias + BOFF_L0, 64, 64, tid);
    stage_b(prm.w[3],  bias + BOFF_L1, 64, 64, tid);
    stage_b(prm.w[5],  bias + BOFF_L2, 64, 64, tid);
    stage_b(prm.w[7],  bias + BOFF_L3, 65, 72, tid);
    stage_b(prm.w[9],  bias + BOFF_R0, 64, 64, tid);
    stage_b(prm.w[11], bias + BOFF_R1, 64, 64, tid);
    stage_b(prm.w[13], bias + BOFF_R2,  3,  8, tid);
    __syncthreads();

    const u32 whi_s = (u32)__cvta_generic_to_shared(whi);
    const u32 wlo_s = (u32)__cvta_generic_to_shared(wlo);
    const u32 adj56 = lane_adj<56>(lane);
    const u32 adj72 = lane_adj<72>(lane);
    const u32 adj88 = lane_adj<88>(lane);
    const u32 sL0h = whi_s + WOFF_L0*2 + adj56, sL0l = wlo_s + WOFF_L0*2 + adj56;
    const u32 sL1h = whi_s + WOFF_L1*2 + adj72, sL1l = wlo_s + WOFF_L1*2 + adj72;
    const u32 sL2h = whi_s + WOFF_L2*2 + adj72, sL2l = wlo_s + WOFF_L2*2 + adj72;
    const u32 sL3h = whi_s + WOFF_L3*2 + adj72, sL3l = wlo_s + WOFF_L3*2 + adj72;
    const u32 sR0h = whi_s + WOFF_R0*2 + adj88, sR0l = wlo_s + WOFF_R0*2 + adj88;
    const u32 sR1h = whi_s + WOFF_R1*2 + adj72, sR1l = wlo_s + WOFF_R1*2 + adj72;
    const u32 sR2h = whi_s + WOFF_R2*2 + adj72, sR2l = wlo_s + WOFF_R2*2 + adj72;

    const int ntiles = n / TILE_PTS;
    int tile = blockIdx.x;
    if (tile >= ntiles) return;

    // prefetch state: enc A-frags (12 u32) + dirs (6 f32) for current tile
    u32 pf[12];
    float pdx0, pdy0, pdz0, pdx1, pdy1, pdz1;

    auto prefetch = [&](int tl) {
        int pt0 = tl * TILE_PTS + rg * 16 + qr;
        int pt1 = pt0 + 8;
        const u32* e0 = g_enc + (size_t)pt0 * LVLS;
        const u32* e1 = g_enc + (size_t)pt1 * LVLS;
#pragma unroll
        for (int kt = 0; kt < 3; kt++) {
            pf[4*kt+0] = __ldg(e0 + qm + 8 * kt);
            pf[4*kt+1] = __ldg(e1 + qm + 8 * kt);
            pf[4*kt+2] = __ldg(e0 + qm + 8 * kt + 4);
            pf[4*kt+3] = __ldg(e1 + qm + 8 * kt + 4);
        }
        pdx0 = __ldg(dirs + pt0 * 3 + 0);
        pdy0 = __ldg(dirs + pt0 * 3 + 1);
        pdz0 = __ldg(dirs + pt0 * 3 + 2);
        pdx1 = __ldg(dirs + pt1 * 3 + 0);
        pdy1 = __ldg(dirs + pt1 * 3 + 1);
        pdz1 = __ldg(dirs + pt1 * 3 + 2);
    };

    prefetch(tile);

    while (true) {
        const int base = tile * TILE_PTS;
        const int next = tile + gridDim.x;
        const bool g = (next < ntiles);

        // consume prefetched values
        u32 ah[20], al[20];
#pragma unroll
        for (int i = 0; i < 12; i++) ah[i] = pf[i];
        float dxA = pdx0, dyA = pdy0, dzA = pdz0;
        float dxB = pdx1, dyB = pdy1, dzB = pdz1;

        if (g) prefetch(next);   // LDGs in flight across whole tile

        float acc[8][4];
        run_layer_l0<8, 56>(ah, sL0h, sL0l, bias + BOFF_L0, acc, qm);

        frags_gelu<4>(acc, ah, al);
        run_layer_lds<0, 4, 8, 72, true>(ah, al, sL1h, sL1l,
                                         bias + BOFF_L1, acc, qm);
        frags_gelu<4>(acc, ah, al);
        run_layer_lds<0, 4, 8, 72, true>(ah, al, sL2h, sL2l,
                                         bias + BOFF_L2, acc, qm);
        frags_gelu<4>(acc, ah, al);
        float acc9[9][4];
        run_layer_lds<0, 4, 9, 72, true>(ah, al, sL3h, sL3l,
                                         bias + BOFF_L3, acc9, qm);

        // density out
        if (qm == 0) {
            int pA = base + rg * 16 + qr;
            out[(size_t)3 * n + pA]     = softplus_f(acc9[0][0]);
            out[(size_t)3 * n + pA + 8] = softplus_f(acc9[0][2]);
        }
        // SH from prefetched dirs
        float shA[9], shB[9];
        shA[0] = 0.28209479177387814f;
        shA[1] = -0.48860251190291987f * dyA;
        shA[2] =  0.48860251190291987f * dzA;
        shA[3] = -0.48860251190291987f * dxA;
        shA[4] =  1.0925484305920792f  * dxA * dyA;
        shA[5] = -1.0925484305920792f  * dyA * dzA;
        shA[6] =  0.31539156525252005f * (3.0f * dzA * dzA - 1.0f);
        shA[7] = -1.0925484305920792f  * dxA * dzA;
        shA[8] =  0.5462742152960396f  * (dxA * dxA - dyA * dyA);
        shB[0] = 0.28209479177387814f;
        shB[1] = -0.48860251190291987f * dyB;
        shB[2] =  0.48860251190291987f * dzB;
        shB[3] = -0.48860251190291987f * dxB;
        shB[4] =  1.0925484305920792f  * dxB * dyB;
        shB[5] = -1.0925484305920792f  * dyB * dzB;
        shB[6] =  0.31539156525252005f * (3.0f * dzB * dzB - 1.0f);
        shB[7] = -1.0925484305920792f  * dxB * dzB;
        shB[8] =  0.5462742152960396f  * (dxB * dxB - dyB * dyB);

        // R0 A-frags: cols 0..63 gelu(fad), k-tile 4 = col64 + SH
        frags_gelu<4>(acc9, ah, al);
        {
            float e64A = gelu_exact(acc9[8][0]);
            float e64B = gelu_exact(acc9[8][2]);
            float v0A, v1A, v2A, v3A, v0B, v1B, v2B, v3B;
            if (qm == 0) {
                v0A = e64A;   v1A = shA[0]; v2A = shA[7]; v3A = shA[8];
                v0B = e64B;   v1B = shB[0]; v2B = shB[7]; v3B = shB[8];
            } else if (qm == 1) {
                v0A = shA[1]; v1A = shA[2]; v2A = 0.0f;   v3A = 0.0f;
                v0B = shB[1]; v1B = shB[2]; v2B = 0.0f;   v3B = 0.0f;
            } else if (qm == 2) {
                v0A = shA[3]; v1A = shA[4]; v2A = 0.0f;   v3A = 0.0f;
                v0B = shB[3]; v1B = shB[4]; v2B = 0.0f;   v3B = 0.0f;
            } else {
                v0A = shA[5]; v1A = shA[6]; v2A = 0.0f;   v3A = 0.0f;
                v0B = shB[5]; v1B = shB[6]; v2B = 0.0f;   v3B = 0.0f;
            }
            pack_split2(v0A, v1A, ah[16], al[16]);
            pack_split2(v0B, v1B, ah[17], al[17]);
            pack_split2(v2A, v3A, ah[18], al[18]);
            pack_split2(v2B, v3B, ah[19], al[19]);
        }

        run_layer_lds<0, 5, 8, 88, true>(ah, al, sR0h, sR0l,
                                         bias + BOFF_R0, acc, qm);
        frags_gelu<4>(acc, ah, al);
        run_layer_lds<0, 4, 8, 72, true>(ah, al, sR1h, sR1l,
                                         bias + BOFF_R1, acc, qm);
        frags_gelu<4>(acc, ah, al);
        {
            float acc1[1][4];
            run_layer_lds<0, 4, 1, 72, true>(ah, al, sR2h, sR2l,
                                             bias + BOFF_R2, acc1, qm);
            int pt0 = base + rg * 16 + qr;
            int pt1 = pt0 + 8;
            if (qm == 0) {
                out[pt0 * 3 + 0] = sigmoid_f(acc1[0][0]);
                out[pt0 * 3 + 1] = sigmoid_f(acc1[0][1]);
                out[pt1 * 3 + 0] = sigmoid_f(acc1[0][2]);
                out[pt1 * 3 + 1] = sigmoid_f(acc1[0][3]);
            } else if (qm == 1) {
                out[pt0 * 3 + 2] = sigmoid_f(acc1[0][0]);
                out[pt1 * 3 + 2] = sigmoid_f(acc1[0][2]);
            }
        }

        if (!g) break;
        tile = next;
    }
}

extern "C" void kernel_launch(void* const* d_in, const int* in_sizes, int n_in,
                              void* d_out, int out_size)
{
    const float* pts   = (const float*)d_in[0];
    const float* dirs  = (const float*)d_in[1];
    const float* table = (const float*)d_in[2];

    WPtrs prm;
    for (int a = 0; a < 14; a++) prm.w[a] = (const float*)d_in[3 + a];

    int n = in_sizes[0] / 3;

    ResArr res;
    double b = exp((log(2048.0) - log(16.0)) / 23.0);
    for (int l = 0; l < LVLS; l++)
        res.r[l] = (float)floor(16.0 * pow(b, (double)l));

    // Kernel 1: gather (one thread per point-level)
    {
        int blocks = (n * LVLS + 191) / 192;   // 65536 for N=524288
        gather_kernel<<<blocks, 192>>>(pts, table, res, n);
    }

    // Kernel 2: MLP
    {
        cudaFuncSetAttribute(mlp_kernel,
                             cudaFuncAttributeMaxDynamicSharedMemorySize,
                             SMEM_BYTES);
        int dev = 0, sms = 148;
        cudaGetDevice(&dev);
        cudaDeviceGetAttribute(&sms, cudaDevAttrMultiProcessorCount, dev);
        int ntiles = n / TILE_PTS;
        int blocks = (sms < ntiles) ? sms : ntiles;
        mlp_kernel<<<blocks, NTHREADS, SMEM_BYTES>>>(
            dirs, prm, (float*)d_out, n);
    }
}